// round 3
// baseline (speedup 1.0000x reference)
#include <cuda_runtime.h>
#include <cuda_bf16.h>
#include <cstdint>

// Problem constants (fixed by the dataset)
constexpr int B  = 8;
constexpr int NN = 10000;
constexpr int E  = 160000;
constexpr int F  = 128;   // GCN feature dim
constexpr int H  = 256;   // hidden dim
constexpr int BNN = B * NN;          // 80000 rows
constexpr float NEG_SLOPE = 0.01f;

// Scratch (allocation-free: __device__ globals)
__device__ float g_dinv[BNN];                       // degree -> d^{-1/2}
__device__ float g_xw [(size_t)BNN * F];            // x @ Wc, later reused for relu(agg)+x0
__device__ float g_agg[(size_t)BNN * F];            // aggregated messages
__device__ float g_h1 [(size_t)BNN * H];            // hidden activations

// ---------------------------------------------------------------------------
// Degree kernels  (edge_index is int32: JAX default x64-disabled downcasts)
// ---------------------------------------------------------------------------
__global__ void init_deg_kernel() {
    int i = blockIdx.x * blockDim.x + threadIdx.x;
    if (i < BNN) g_dinv[i] = 1.0f;   // self loop
}

__global__ void count_deg_kernel(const int* __restrict__ ei) {
    int i = blockIdx.x * blockDim.x + threadIdx.x;
    if (i >= B * E) return;
    int b = i / E;
    int e = i - b * E;
    int dst = ei[b * 2 * E + E + e];
    atomicAdd(&g_dinv[b * NN + dst], 1.0f);
}

__global__ void rsqrt_deg_kernel() {
    int i = blockIdx.x * blockDim.x + threadIdx.x;
    if (i < BNN) g_dinv[i] = rsqrtf(g_dinv[i]);  // deg >= 1 always
}

// ---------------------------------------------------------------------------
// SGEMM: C[M,N] = act(A[M,K] @ Bm[K,N] + bias)  (fp32, 128x128x16 tiles)
// ---------------------------------------------------------------------------
constexpr int BMt = 128, BNt = 128, BKt = 16, TM = 8, TN = 8;

template <int ACT>  // 0 = none, 1 = leaky_relu
__global__ __launch_bounds__(256)
void sgemm_kernel(const float* __restrict__ A, const float* __restrict__ Bm,
                  const float* __restrict__ bias, float* __restrict__ C,
                  int M, int Nn, int K) {
    __shared__ float As[BKt][BMt];
    __shared__ float Bs[BKt][BNt];

    const int tid = threadIdx.x;
    const int bx = blockIdx.x, by = blockIdx.y;

    const float* Ablk = A + (long long)by * BMt * K;
    const float* Bblk = Bm + bx * BNt;

    float acc[TM][TN];
    #pragma unroll
    for (int i = 0; i < TM; i++)
        #pragma unroll
        for (int j = 0; j < TN; j++) acc[i][j] = 0.0f;

    const int tRow = tid / (BNt / TN);   // 0..15
    const int tCol = tid % (BNt / TN);   // 0..15

    const int aRow = tid / (BKt / 4);    // 0..63
    const int aCol = tid % (BKt / 4);    // 0..3  (float4 column)
    const int bRow = tid / (BNt / 4);    // 0..7
    const int bCol = tid % (BNt / 4);    // 0..31 (float4 column)

    for (int kt = 0; kt < K; kt += BKt) {
        #pragma unroll
        for (int r = 0; r < 2; r++) {
            float4 v = *(const float4*)(Ablk + (long long)(aRow + r * 64) * K + kt + aCol * 4);
            As[aCol * 4 + 0][aRow + r * 64] = v.x;
            As[aCol * 4 + 1][aRow + r * 64] = v.y;
            As[aCol * 4 + 2][aRow + r * 64] = v.z;
            As[aCol * 4 + 3][aRow + r * 64] = v.w;
        }
        #pragma unroll
        for (int r = 0; r < 2; r++) {
            float4 v = *(const float4*)(Bblk + (long long)(kt + bRow + r * 8) * Nn + bCol * 4);
            *(float4*)&Bs[bRow + r * 8][bCol * 4] = v;
        }
        __syncthreads();

        #pragma unroll
        for (int k = 0; k < BKt; k++) {
            float ra[TM], rb[TN];
            #pragma unroll
            for (int i = 0; i < TM; i++) ra[i] = As[k][tRow * TM + i];
            #pragma unroll
            for (int j = 0; j < TN; j++) rb[j] = Bs[k][tCol * TN + j];
            #pragma unroll
            for (int i = 0; i < TM; i++)
                #pragma unroll
                for (int j = 0; j < TN; j++)
                    acc[i][j] += ra[i] * rb[j];
        }
        __syncthreads();
    }

    float* Cblk = C + (long long)by * BMt * Nn + bx * BNt;
    #pragma unroll
    for (int i = 0; i < TM; i++) {
        int row = tRow * TM + i;
        #pragma unroll
        for (int j = 0; j < TN; j += 4) {
            float4 v;
            float* pv = &v.x;
            #pragma unroll
            for (int q = 0; q < 4; q++) {
                float c = acc[i][j + q];
                if (bias) c += bias[bx * BNt + tCol * TN + j + q];
                if (ACT == 1) c = c > 0.0f ? c : NEG_SLOPE * c;
                pv[q] = c;
            }
            *(float4*)(Cblk + (long long)row * Nn + tCol * TN + j) = v;
        }
    }
}

// ---------------------------------------------------------------------------
// Self-loop init: agg[n,:] = dinv[n]^2 * xw[n,:]
// ---------------------------------------------------------------------------
__global__ void selfloop_kernel() {
    int i = blockIdx.x * blockDim.x + threadIdx.x;   // over BNN * (F/4)
    if (i >= BNN * (F / 4)) return;
    int row = i / (F / 4);
    float d = g_dinv[row];
    float s = d * d;
    float4 v = ((const float4*)g_xw)[i];
    float4 o;
    o.x = s * v.x; o.y = s * v.y; o.z = s * v.z; o.w = s * v.w;
    ((float4*)g_agg)[i] = o;
}

// ---------------------------------------------------------------------------
// Edge scatter: one warp per edge, scalar red.global.add.f32 (atomicAdd)
// ---------------------------------------------------------------------------
__global__ __launch_bounds__(256)
void scatter_kernel(const int* __restrict__ ei) {
    int gw = (blockIdx.x * blockDim.x + threadIdx.x) >> 5;
    int lane = threadIdx.x & 31;
    if (gw >= B * E) return;
    int b = gw / E;
    int e = gw - b * E;
    const int* eb = ei + b * 2 * E;
    int src = eb[e];
    int dst = eb[E + e];
    float norm = g_dinv[b * NN + src] * g_dinv[b * NN + dst];
    const float4* s = (const float4*)(g_xw + (long long)(b * NN + src) * F);
    float4 v = s[lane];
    float* d = g_agg + (long long)(b * NN + dst) * F + lane * 4;
    atomicAdd(d + 0, v.x * norm);
    atomicAdd(d + 1, v.y * norm);
    atomicAdd(d + 2, v.z * norm);
    atomicAdd(d + 3, v.w * norm);
}

// ---------------------------------------------------------------------------
// Post: out1 = relu(agg + bc) + x0   (written into g_xw, reused)
// ---------------------------------------------------------------------------
__global__ void post_kernel(const float* __restrict__ x0, const float* __restrict__ bc) {
    int i = blockIdx.x * blockDim.x + threadIdx.x;   // over BNN * (F/4)
    if (i >= BNN * (F / 4)) return;
    int c4 = i & (F / 4 - 1);
    float4 a = ((const float4*)g_agg)[i];
    float4 bb = ((const float4*)bc)[c4];
    float4 x = ((const float4*)x0)[i];
    float4 o;
    o.x = fmaxf(a.x + bb.x, 0.0f) + x.x;
    o.y = fmaxf(a.y + bb.y, 0.0f) + x.y;
    o.z = fmaxf(a.z + bb.z, 0.0f) + x.z;
    o.w = fmaxf(a.w + bb.w, 0.0f) + x.w;
    ((float4*)g_xw)[i] = o;
}

// ---------------------------------------------------------------------------
extern "C" void kernel_launch(void* const* d_in, const int* in_sizes, int n_in,
                              void* d_out, int out_size) {
    const float* x0 = (const float*)d_in[0];       // [B,N,F]
    const int*   ei = (const int*)d_in[1];         // [B,2,E] int32 (JAX x64 off)
    const float* Wc = (const float*)d_in[2];       // [F,F]
    const float* bc = (const float*)d_in[3];       // [F]
    const float* W1 = (const float*)d_in[4];       // [F,H]
    const float* b1 = (const float*)d_in[5];       // [H]
    const float* W2 = (const float*)d_in[6];       // [H,H]
    const float* b2 = (const float*)d_in[7];       // [H]
    float* out = (float*)d_out;                    // [B,N,H]

    float *xw, *agg, *h1;
    cudaGetSymbolAddress((void**)&xw,  g_xw);
    cudaGetSymbolAddress((void**)&agg, g_agg);
    cudaGetSymbolAddress((void**)&h1,  g_h1);

    // 1) degrees -> dinv
    init_deg_kernel<<<(BNN + 255) / 256, 256>>>();
    count_deg_kernel<<<(B * E + 255) / 256, 256>>>(ei);
    rsqrt_deg_kernel<<<(BNN + 255) / 256, 256>>>();

    // 2) xw = x0 @ Wc   (M=80000, N=128, K=128)
    {
        dim3 grid(F / BNt, BNN / BMt);
        sgemm_kernel<0><<<grid, 256>>>(x0, Wc, nullptr, xw, BNN, F, F);
    }

    // 3) agg init with self loop, then edge scatter
    selfloop_kernel<<<(BNN * (F / 4) + 255) / 256, 256>>>();
    scatter_kernel<<<(B * E * 32 + 255) / 256, 256>>>(ei);

    // 4) out1 = relu(agg + bc) + x0  (into g_xw)
    post_kernel<<<(BNN * (F / 4) + 255) / 256, 256>>>(x0, bc);

    // 5) h1 = leaky_relu(out1 @ W1 + b1)  (M=80000, N=256, K=128)
    {
        dim3 grid(H / BNt, BNN / BMt);
        sgemm_kernel<1><<<grid, 256>>>(xw, W1, b1, h1, BNN, H, F);
    }

    // 6) out = leaky_relu(h1 @ W2 + b2)  (M=80000, N=256, K=256)
    {
        dim3 grid(H / BNt, BNN / BMt);
        sgemm_kernel<1><<<grid, 256>>>(h1, W2, b2, out, BNN, H, H);
    }
}